// round 16
// baseline (speedup 1.0000x reference)
#include <cuda_runtime.h>
#include <cstdint>

#define IN_F   8192
#define OUT_F  8192
#define THR    50.0f
#define NT     256
#define NV     (IN_F / 4)         // 2048 float4 per row
#define FPT    (NV / NT)          // 8 float4 per thread — one burst = full row
#define HALF   (FPT / 2)          // elig burst split across the barrier

__global__ __launch_bounds__(NT)
void snn_final2_kernel(const float* __restrict__ x,
                       const float* __restrict__ syn,
                       const float* __restrict__ mp,
                       const float* __restrict__ thr,
                       const float* __restrict__ elig,
                       float* __restrict__ out) {
    __shared__ float red[NT / 32];
    const int o = blockIdx.x;
    const int t = threadIdx.x;

    const float4* x4 = reinterpret_cast<const float4*>(x);   // 32 KB, L1-resident
    const float4* s4 = reinterpret_cast<const float4*>(syn  + (size_t)o * IN_F);
    const float4* e4 = reinterpret_cast<const float4*>(elig + (size_t)o * IN_F);

    // ── Maximum early in-flight depth: 8 syn + 4 elig LDG.128 per thread,
    //    all issued before any dependent compute ──
    float4 s[FPT];
    #pragma unroll
    for (int j = 0; j < FPT; j++)
        s[j] = __ldcs(&s4[t + j * NT]);

    float4 e[HALF];
    #pragma unroll
    for (int j = 0; j < HALF; j++)
        e[j] = __ldcs(&e4[t + j * NT]);          // independent — fly with syn

    // ── Phase 1 accumulate (4 independent chains) ──
    float a0 = 0.0f, a1 = 0.0f, a2 = 0.0f, a3 = 0.0f;
    #pragma unroll
    for (int j = 0; j < FPT; j++) {
        float4 xv = __ldg(&x4[t + j * NT]);      // L1 hit after warm-up
        a0 += (s[j].x > THR ? xv.x : 0.0f);
        a1 += (s[j].y > THR ? xv.y : 0.0f);
        a2 += (s[j].z > THR ? xv.z : 0.0f);
        a3 += (s[j].w > THR ? xv.w : 0.0f);
    }

    float acc = (a0 + a1) + (a2 + a3);
    #pragma unroll
    for (int off = 16; off > 0; off >>= 1)
        acc += __shfl_down_sync(0xffffffffu, acc, off);
    if ((t & 31) == 0) red[t >> 5] = acc;
    __syncthreads();                             // first elig half still in flight

    // Second half immediately post-barrier — overlaps finalize + first-half consume
    float4 e2[HALF];
    #pragma unroll
    for (int j = 0; j < HALF; j++)
        e2[j] = __ldcs(&e4[t + (HALF + j) * NT]);

    float cur = 0.0f;
    #pragma unroll
    for (int w = 0; w < NT / 32; w++) cur += red[w];
    const float v  = __ldg(mp + o) * 0.6f + cur;
    const float sp = (v >= __ldg(thr + o)) ? 1.0f : 0.0f;
    if (t == 0) {
        out[o] = sp;                             // spikes
        out[OUT_F + o] = v * (1.0f - sp) * 0.3f; // v_new
    }

    // ── Phase 2: consume both halves → trace ──
    float4* o4 = reinterpret_cast<float4*>(out + 2 * (size_t)OUT_F
                                               + (size_t)o * IN_F);
    #pragma unroll
    for (int j = 0; j < HALF; j++) {
        float4 xv = __ldg(&x4[t + j * NT]);
        float4 r;
        r.x = fminf(fmaxf(fmaf(e[j].x, 0.7f, sp * xv.x), 0.0f), 3.0f);
        r.y = fminf(fmaxf(fmaf(e[j].y, 0.7f, sp * xv.y), 0.0f), 3.0f);
        r.z = fminf(fmaxf(fmaf(e[j].z, 0.7f, sp * xv.z), 0.0f), 3.0f);
        r.w = fminf(fmaxf(fmaf(e[j].w, 0.7f, sp * xv.w), 0.0f), 3.0f);
        __stcs(&o4[t + j * NT], r);
    }
    #pragma unroll
    for (int j = 0; j < HALF; j++) {
        float4 xv = __ldg(&x4[t + (HALF + j) * NT]);
        float4 r;
        r.x = fminf(fmaxf(fmaf(e2[j].x, 0.7f, sp * xv.x), 0.0f), 3.0f);
        r.y = fminf(fmaxf(fmaf(e2[j].y, 0.7f, sp * xv.y), 0.0f), 3.0f);
        r.z = fminf(fmaxf(fmaf(e2[j].z, 0.7f, sp * xv.z), 0.0f), 3.0f);
        r.w = fminf(fmaxf(fmaf(e2[j].w, 0.7f, sp * xv.w), 0.0f), 3.0f);
        __stcs(&o4[t + (HALF + j) * NT], r);
    }
}

extern "C" void kernel_launch(void* const* d_in, const int* in_sizes, int n_in,
                              void* d_out, int out_size) {
    const float* x    = (const float*)d_in[0];  // spike_input [1, 8192]
    const float* syn  = (const float*)d_in[1];  // synapse_states [8192, 8192]
    const float* mp   = (const float*)d_in[2];  // membrane_potential [8192]
    const float* thr  = (const float*)d_in[3];  // adaptive_threshold [8192]
    const float* elig = (const float*)d_in[4];  // eligibility_trace [8192, 8192]
    float* out = (float*)d_out;                 // [spikes | v_new | trace_new]

    snn_final2_kernel<<<OUT_F, NT>>>(x, syn, mp, thr, elig, out);
}